// round 1
// baseline (speedup 1.0000x reference)
#include <cuda_runtime.h>
#include <math.h>

#define D 64
#define C 128
#define H 512
#define BATCH 4096
#define TM 32
#define NTHREADS 256

// Permuted + masked weights (built by prep kernel each launch; idempotent).
__device__ float g_W1p[(D + C) * H];   // [in][p]  in-major, masked, hidden perm
__device__ float g_W2p[H * H];         // [j][p]   j = reduction dim (sorted), p sorted
__device__ float g_W3pp[D * H * 2];    // [i][p][2] (mean col i, prescale col D+i), masked
__device__ float g_b1p[H];
__device__ float g_b2p[H];

// Hidden degrees: m_h[k] = (k % 63) + 1. Sorted by degree ascending (ties by k).
// Residues 0..7 occur 9x (degrees 1..8), residues 8..62 occur 8x (degrees 9..63).
__device__ __forceinline__ int permk(int p) {
    if (p < 72) { int d = p / 9; int t = p - 9 * d; return d + 63 * t; }
    int q = p - 72; int d8 = q >> 3; int t = q & 7; return 8 + d8 + 63 * t;
}
__device__ __forceinline__ int degp(int p) {
    return (p < 72) ? (p / 9 + 1) : ((p - 72) / 8 + 9);
}
// count of hidden units with degree <= d
__device__ __forceinline__ int cntd(int d) {
    return (d <= 0) ? 0 : (d <= 8 ? 9 * d : 8 * d + 8);
}

__global__ void prep_kernel(const float* __restrict__ W1, const float* __restrict__ b1,
                            const float* __restrict__ W2, const float* __restrict__ b2,
                            const float* __restrict__ W3) {
    const int NA = (D + C) * H;
    const int NB = H * H;
    const int NC = D * H;
    const int total = NA + NB + NC + 2 * H;
    for (int idx = blockIdx.x * blockDim.x + threadIdx.x; idx < total;
         idx += gridDim.x * blockDim.x) {
        if (idx < NA) {
            int in = idx >> 9, p = idx & 511;
            float m = (in < D) ? ((degp(p) >= in + 1) ? 1.f : 0.f) : 1.f;
            g_W1p[idx] = W1[in * H + permk(p)] * m;
        } else if (idx < NA + NB) {
            int t = idx - NA;
            int j = t >> 9, p = t & 511;
            g_W2p[t] = (degp(p) >= degp(j)) ? W2[permk(j) * H + permk(p)] : 0.f;
        } else if (idx < NA + NB + NC) {
            int t = idx - NA - NB;
            int i = t >> 9, p = t & 511;
            int k = permk(p);
            bool m = (degp(p) <= i);   // m_out = i+1 > deg  <=>  deg <= i
            g_W3pp[t * 2 + 0] = m ? W3[k * (2 * D) + i] : 0.f;
            g_W3pp[t * 2 + 1] = m ? W3[k * (2 * D) + D + i] : 0.f;
        } else {
            int t = idx - NA - NB - NC;
            if (t < H) g_b1p[t] = b1[permk(t)];
            else       g_b2p[t - H] = b2[permk(t - H)];
        }
    }
}

// Dynamic smem layout (floats):
//   h1s[H*TM]        : pre-activation h1, layout h1s[j*32 + r]   (64 KB)
//   w2s[32*128]      : staged W2 tile (also reused for ctx transpose) (16 KB)
//   zsh[TM]          : z values of current step
//   red[64]          : per-row mean (0..31) / prescale (32..63) partials
#define SMEM_FLOATS (H * TM + 32 * 128 + TM + 64)
#define SMEM_BYTES (SMEM_FLOATS * 4)

__global__ __launch_bounds__(NTHREADS, 1)
void made_main(const float* __restrict__ qc, const float* __restrict__ eps,
               const float* __restrict__ b3, float* __restrict__ out) {
    extern __shared__ float sm[];
    float* h1s = sm;                 // [512][32]
    float* w2s = sm + H * TM;        // [32][128]
    float* zsh = w2s + 32 * 128;     // [32]
    float* red = zsh + TM;           // [64]

    const int tid  = threadIdx.x;
    const int r0   = blockIdx.x * TM;
    const int warp = tid >> 5, lane = tid & 31;
    const int rg   = lane & 7;       // rows rg*4 .. rg*4+3
    const int cg   = lane >> 3;      // col sub-offset cg*4
    const int colo = warp * 16 + (cg << 2);  // column offset within 128-chunk

    // ---- stage context rows transposed into w2s: ctxs[c*32 + r] ----
    for (int idx = tid; idx < TM * C; idx += NTHREADS) {
        int r = idx >> 7, c = idx & 127;
        w2s[c * 32 + r] = qc[(r0 + r) * C + c];
    }
    __syncthreads();

    // ---- h1_pre init: ctx @ W1p[context rows] + b1p ----
    for (int o = tid; o < H * TM; o += NTHREADS) {
        int p = o >> 5, r = o & 31;
        float a = g_b1p[p];
#pragma unroll 8
        for (int c = 0; c < C; ++c)
            a += w2s[c * 32 + r] * g_W1p[(D + c) * H + p];
        h1s[p * 32 + r] = a;
    }

    // ---- 64 autoregressive steps ----
    for (int i = 0; i < D; ++i) {
        const int n2 = cntd(i);      // needed h2 cols = sorted prefix [0, n2)
        if (tid < 64) red[tid] = 0.f;
        float mpm[4] = {0.f, 0.f, 0.f, 0.f};
        float mpp[4] = {0.f, 0.f, 0.f, 0.f};
        __syncthreads();             // red zeroed; prev-step h1 update visible

        for (int pc = 0; pc < n2; pc += 128) {
            const int lastneed = min(pc + 127, n2 - 1);
            int jlim = cntd(degp(lastneed));       // rows needed for needed cols
            jlim = min(H, (jlim + 31) & ~31);
            const int mycol = pc + colo;

            float acc[4][4];
#pragma unroll
            for (int cc = 0; cc < 4; ++cc) {
                float b = g_b2p[mycol + cc];
                acc[0][cc] = b; acc[1][cc] = b; acc[2][cc] = b; acc[3][cc] = b;
            }

            for (int jc = 0; jc < jlim; jc += 32) {
                __syncthreads();
                // stage W2p tile [32 rows][128 cols]
                for (int t = tid; t < 1024; t += NTHREADS) {
                    int jj = t >> 5, c4 = t & 31;
                    *(float4*)&w2s[(jj << 7) + (c4 << 2)] =
                        *(const float4*)&g_W2p[(jc + jj) * H + pc + (c4 << 2)];
                }
                __syncthreads();
#pragma unroll
                for (int jj = 0; jj < 32; ++jj) {
                    float4 h = *(const float4*)&h1s[((jc + jj) << 5) + (rg << 2)];
                    h.x = fmaxf(h.x, 0.f); h.y = fmaxf(h.y, 0.f);
                    h.z = fmaxf(h.z, 0.f); h.w = fmaxf(h.w, 0.f);
                    float4 w = *(const float4*)&w2s[(jj << 7) + colo];
                    acc[0][0] += h.x * w.x; acc[0][1] += h.x * w.y;
                    acc[0][2] += h.x * w.z; acc[0][3] += h.x * w.w;
                    acc[1][0] += h.y * w.x; acc[1][1] += h.y * w.y;
                    acc[1][2] += h.y * w.z; acc[1][3] += h.y * w.w;
                    acc[2][0] += h.z * w.x; acc[2][1] += h.z * w.y;
                    acc[2][2] += h.z * w.z; acc[2][3] += h.z * w.w;
                    acc[3][0] += h.w * w.x; acc[3][1] += h.w * w.y;
                    acc[3][2] += h.w * w.z; acc[3][3] += h.w * w.w;
                }
            }

            // relu + project onto W3 cols (i, D+i); masked weights zero out
            // any cols in this chunk with deg > i (their garbage h2 is harmless).
#pragma unroll
            for (int cc = 0; cc < 4; ++cc) {
                float wm = g_W3pp[((i << 9) + mycol + cc) * 2 + 0];
                float wp = g_W3pp[((i << 9) + mycol + cc) * 2 + 1];
#pragma unroll
                for (int rr = 0; rr < 4; ++rr) {
                    float h2 = fmaxf(acc[rr][cc], 0.f);
                    mpm[rr] += h2 * wm;
                    mpp[rr] += h2 * wp;
                }
            }
        }

        // reduce over the 4 col-groups within the warp (lanes differing in bits 3,4)
#pragma unroll
        for (int rr = 0; rr < 4; ++rr) {
            mpm[rr] += __shfl_xor_sync(0xffffffff, mpm[rr], 8);
            mpm[rr] += __shfl_xor_sync(0xffffffff, mpm[rr], 16);
            mpp[rr] += __shfl_xor_sync(0xffffffff, mpp[rr], 8);
            mpp[rr] += __shfl_xor_sync(0xffffffff, mpp[rr], 16);
        }
        if (lane < 8) {
#pragma unroll
            for (int rr = 0; rr < 4; ++rr) {
                atomicAdd(&red[lane * 4 + rr], mpm[rr]);
                atomicAdd(&red[32 + lane * 4 + rr], mpp[rr]);
            }
        }
        __syncthreads();

        if (tid < TM) {
            float mean = red[tid] + b3[i];
            float pres = red[32 + tid] + b3[D + i];
            // stable softplus = max(x,0) + log1p(exp(-|x|))
            float sp = fmaxf(pres, 0.f) + log1pf(expf(-fabsf(pres)));
            float z = mean + sp * eps[(r0 + tid) * D + i];
            out[(r0 + tid) * D + i] = z;
            zsh[tid] = z;
        }
        __syncthreads();

        // rank-1 h1_pre update: only hidden units with deg >= i+1 (sorted suffix)
        const int s0 = n2;
        const int nupd = (H - s0) * TM;
        for (int u = tid; u < nupd; u += NTHREADS) {
            int p = s0 + (u >> 5), r = u & 31;
            h1s[p * 32 + r] += zsh[r] * g_W1p[i * H + p];
        }
        // top-of-loop __syncthreads orders update before next step's reads
    }
}

extern "C" void kernel_launch(void* const* d_in, const int* in_sizes, int n_in,
                              void* d_out, int out_size) {
    const float* q   = (const float*)d_in[0];  // (4096, 128)
    const float* eps = (const float*)d_in[1];  // (4096, 64)
    const float* W1  = (const float*)d_in[2];  // (192, 512)
    const float* b1  = (const float*)d_in[3];  // (512,)
    const float* W2  = (const float*)d_in[4];  // (512, 512)
    const float* b2  = (const float*)d_in[5];  // (512,)
    const float* W3  = (const float*)d_in[6];  // (512, 128)
    const float* b3  = (const float*)d_in[7];  // (128,)
    float* out = (float*)d_out;                // (4096, 64)

    cudaFuncSetAttribute(made_main, cudaFuncAttributeMaxDynamicSharedMemorySize,
                         SMEM_BYTES);

    prep_kernel<<<408, 256>>>(W1, b1, W2, b2, W3);
    made_main<<<BATCH / TM, NTHREADS, SMEM_BYTES>>>(q, eps, b3, out);
}

// round 2
// speedup vs baseline: 1.1412x; 1.1412x over previous
#include <cuda_runtime.h>
#include <math.h>

#define D 64
#define C 128
#define H 512
#define BATCH 4096
#define TM 16
#define NTHREADS 256

// Permuted + masked weights (built by prep kernel each launch; idempotent).
__device__ float g_W1p[(D + C) * H];   // [in][p]  in-major, masked, hidden perm
__device__ float g_W2p[H * H];         // [j][p]   j = reduction dim (sorted), p sorted
__device__ float g_W3pp[D * H * 2];    // [i][p][2] (mean col i, prescale col D+i), masked
__device__ float g_b1p[H];
__device__ float g_b2p[H];

// Hidden degrees: m_h[k] = (k % 63) + 1. Sorted by degree ascending (ties by k).
// Residues 0..7 occur 9x (degrees 1..8), residues 8..62 occur 8x (degrees 9..63).
__device__ __forceinline__ int permk(int p) {
    if (p < 72) { int d = p / 9; int t = p - 9 * d; return d + 63 * t; }
    int q = p - 72; int d8 = q >> 3; int t = q & 7; return 8 + d8 + 63 * t;
}
__device__ __forceinline__ int degp(int p) {
    return (p < 72) ? (p / 9 + 1) : ((p - 72) / 8 + 9);
}
// count of hidden units with degree <= d
__device__ __forceinline__ int cntd(int d) {
    return (d <= 0) ? 0 : (d <= 8 ? 9 * d : 8 * d + 8);
}

__global__ void prep_kernel(const float* __restrict__ W1, const float* __restrict__ b1,
                            const float* __restrict__ W2, const float* __restrict__ b2,
                            const float* __restrict__ W3) {
    const int NA = (D + C) * H;
    const int NB = H * H;
    const int NC = D * H;
    const int total = NA + NB + NC + 2 * H;
    for (int idx = blockIdx.x * blockDim.x + threadIdx.x; idx < total;
         idx += gridDim.x * blockDim.x) {
        if (idx < NA) {
            int in = idx >> 9, p = idx & 511;
            float m = (in < D) ? ((degp(p) >= in + 1) ? 1.f : 0.f) : 1.f;
            g_W1p[idx] = W1[in * H + permk(p)] * m;
        } else if (idx < NA + NB) {
            int t = idx - NA;
            int j = t >> 9, p = t & 511;
            g_W2p[t] = (degp(p) >= degp(j)) ? W2[permk(j) * H + permk(p)] : 0.f;
        } else if (idx < NA + NB + NC) {
            int t = idx - NA - NB;
            int i = t >> 9, p = t & 511;
            int k = permk(p);
            bool m = (degp(p) <= i);   // m_out = i+1 > deg  <=>  deg <= i
            g_W3pp[t * 2 + 0] = m ? W3[k * (2 * D) + i] : 0.f;
            g_W3pp[t * 2 + 1] = m ? W3[k * (2 * D) + D + i] : 0.f;
        } else {
            int t = idx - NA - NB - NC;
            if (t < H) g_b1p[t] = b1[permk(t)];
            else       g_b2p[t - H] = b2[permk(t - H)];
        }
    }
}

// Dynamic smem layout (floats):
//   h1s[H*TM]  : h1 (pre-act until finalized, then relu'd in place)  [p][r]  32KB
//   ctx[TM*C]  : context rows, row-major                              8KB
//   zsh[TM]    : z values of current step
//   red[2*TM]  : per-row mean (0..15) / prescale (16..31) partials
#define SMEM_FLOATS (H * TM + TM * C + TM + 2 * TM)
#define SMEM_BYTES (SMEM_FLOATS * 4)

__global__ __launch_bounds__(NTHREADS, 2)
void made_main(const float* __restrict__ qc, const float* __restrict__ eps,
               const float* __restrict__ b3, float* __restrict__ out) {
    extern __shared__ float sm[];
    float* h1s = sm;                 // [512][16]
    float* ctx = sm + H * TM;        // [16][128]
    float* zsh = ctx + TM * C;       // [16]
    float* red = zsh + TM;           // [32]

    const int tid  = threadIdx.x;
    const int r0   = blockIdx.x * TM;
    const int warp = tid >> 5, lane = tid & 31;
    const int rg   = lane & 7;                // row group: rows rg*2, rg*2+1
    const int cg   = lane >> 3;               // 0..3
    const int colo = warp * 16 + (cg << 2);   // column offset within 128-chunk

    // ---- stage context rows (row-major, fully coalesced) ----
    for (int idx = tid; idx < TM * C; idx += NTHREADS) {
        int r = idx >> 7, c = idx & 127;
        ctx[idx] = qc[(r0 + r) * C + c];
    }
    if (tid < 2 * TM) red[tid] = 0.f;
    __syncthreads();

    // ---- h1_pre init: ctx @ W1p[context rows] + b1p (no relu yet) ----
    for (int o = tid; o < H * TM; o += NTHREADS) {
        int r = o >> 9, p = o & 511;          // all threads in an iter share r
        float a = __ldg(&g_b1p[p]);
#pragma unroll 4
        for (int c = 0; c < C; c += 4) {
            float4 x = *(const float4*)&ctx[r * C + c];
            a += x.x * __ldg(&g_W1p[(D + c + 0) * H + p]);
            a += x.y * __ldg(&g_W1p[(D + c + 1) * H + p]);
            a += x.z * __ldg(&g_W1p[(D + c + 2) * H + p]);
            a += x.w * __ldg(&g_W1p[(D + c + 3) * H + p]);
        }
        h1s[p * TM + r] = a;
    }

    // ---- 64 autoregressive steps ----
    for (int i = 0; i < D; ++i) {
        __syncthreads();   // prev h1 update + red reset visible
        const int n2 = cntd(i);               // needed h2 cols = sorted prefix
        float mm0 = 0.f, mm1 = 0.f, pp0 = 0.f, pp1 = 0.f;

        for (int pc = 0; pc < n2; pc += 128) {
            const int lastneed = min(pc + 127, n2 - 1);
            const int jlimR = min(H, (cntd(degp(lastneed)) + 7) & ~7);
            const int mycol = pc + colo;

            float4 b2v = __ldg((const float4*)&g_b2p[mycol]);
            float a00 = b2v.x, a01 = b2v.y, a02 = b2v.z, a03 = b2v.w;
            float a10 = b2v.x, a11 = b2v.y, a12 = b2v.z, a13 = b2v.w;

            const float* w2base = g_W2p + mycol;
            const float* hbase  = h1s + (rg << 1);

            for (int jc = 0; jc < jlimR; jc += 8) {
                float2 h[8]; float4 w[8];
#pragma unroll
                for (int u = 0; u < 8; ++u) {
                    h[u] = *(const float2*)&hbase[(jc + u) * TM];
                    w[u] = __ldg((const float4*)(w2base + (jc + u) * H));
                }
#pragma unroll
                for (int u = 0; u < 8; ++u) {
                    a00 += h[u].x * w[u].x; a01 += h[u].x * w[u].y;
                    a02 += h[u].x * w[u].z; a03 += h[u].x * w[u].w;
                    a10 += h[u].y * w[u].x; a11 += h[u].y * w[u].y;
                    a12 += h[u].y * w[u].z; a13 += h[u].y * w[u].w;
                }
            }

            // relu + project onto W3 cols (i, D+i); masked W3 zeroes out
            // any cols in this chunk with deg > i (their garbage h2 is harmless).
            const float* w3 = g_W3pp + (((i << 9) + mycol) << 1);
            float4 wA = __ldg((const float4*)w3);        // (m0,p0,m1,p1)
            float4 wB = __ldg((const float4*)(w3 + 4));  // (m2,p2,m3,p3)
            float h2;
            h2 = fmaxf(a00, 0.f); mm0 += h2 * wA.x; pp0 += h2 * wA.y;
            h2 = fmaxf(a10, 0.f); mm1 += h2 * wA.x; pp1 += h2 * wA.y;
            h2 = fmaxf(a01, 0.f); mm0 += h2 * wA.z; pp0 += h2 * wA.w;
            h2 = fmaxf(a11, 0.f); mm1 += h2 * wA.z; pp1 += h2 * wA.w;
            h2 = fmaxf(a02, 0.f); mm0 += h2 * wB.x; pp0 += h2 * wB.y;
            h2 = fmaxf(a12, 0.f); mm1 += h2 * wB.x; pp1 += h2 * wB.y;
            h2 = fmaxf(a03, 0.f); mm0 += h2 * wB.z; pp0 += h2 * wB.w;
            h2 = fmaxf(a13, 0.f); mm1 += h2 * wB.z; pp1 += h2 * wB.w;
        }

        // reduce over the 4 col-groups within the warp (lane bits 3,4)
        mm0 += __shfl_xor_sync(0xffffffffu, mm0, 8);
        mm0 += __shfl_xor_sync(0xffffffffu, mm0, 16);
        mm1 += __shfl_xor_sync(0xffffffffu, mm1, 8);
        mm1 += __shfl_xor_sync(0xffffffffu, mm1, 16);
        pp0 += __shfl_xor_sync(0xffffffffu, pp0, 8);
        pp0 += __shfl_xor_sync(0xffffffffu, pp0, 16);
        pp1 += __shfl_xor_sync(0xffffffffu, pp1, 8);
        pp1 += __shfl_xor_sync(0xffffffffu, pp1, 16);
        if (lane < 8 && n2 > 0) {
            atomicAdd(&red[(rg << 1) + 0], mm0);
            atomicAdd(&red[(rg << 1) + 1], mm1);
            atomicAdd(&red[TM + (rg << 1) + 0], pp0);
            atomicAdd(&red[TM + (rg << 1) + 1], pp1);
        }
        __syncthreads();

        if (tid < TM) {
            float mean = red[tid] + b3[i];
            float pres = red[TM + tid] + b3[D + i];
            // stable softplus = max(x,0) + log1p(exp(-|x|))
            float sp = fmaxf(pres, 0.f) + log1pf(expf(-fabsf(pres)));
            float z = mean + sp * eps[(r0 + tid) * D + i];
            out[(r0 + tid) * D + i] = z;
            zsh[tid] = z;
            red[tid] = 0.f;                 // reset for next step
            red[TM + tid] = 0.f;
        }
        __syncthreads();

        // rank-1 h1 update: hidden units with deg >= i+1 (sorted suffix).
        // Rows with deg == i+1 are now finalized -> apply relu in place.
        const int s0  = n2;
        const int fin = cntd(i + 1);
        const int nupd = (H - s0) * TM;
        for (int u = tid; u < nupd; u += NTHREADS) {
            int p = s0 + (u >> 4), r = u & 15;
            float v = h1s[p * TM + r] + zsh[r] * __ldg(&g_W1p[i * H + p]);
            if (p < fin) v = fmaxf(v, 0.f);
            h1s[p * TM + r] = v;
        }
        // top-of-loop __syncthreads orders update before next step's reads
    }
}

extern "C" void kernel_launch(void* const* d_in, const int* in_sizes, int n_in,
                              void* d_out, int out_size) {
    const float* q   = (const float*)d_in[0];  // (4096, 128)
    const float* eps = (const float*)d_in[1];  // (4096, 64)
    const float* W1  = (const float*)d_in[2];  // (192, 512)
    const float* b1  = (const float*)d_in[3];  // (512,)
    const float* W2  = (const float*)d_in[4];  // (512, 512)
    const float* b2  = (const float*)d_in[5];  // (512,)
    const float* W3  = (const float*)d_in[6];  // (512, 128)
    const float* b3  = (const float*)d_in[7];  // (128,)
    float* out = (float*)d_out;                // (4096, 64)

    cudaFuncSetAttribute(made_main, cudaFuncAttributeMaxDynamicSharedMemorySize,
                         SMEM_BYTES);

    prep_kernel<<<408, 256>>>(W1, b1, W2, b2, W3);
    made_main<<<BATCH / TM, NTHREADS, SMEM_BYTES>>>(q, eps, b3, out);
}

// round 3
// speedup vs baseline: 2.0172x; 1.7676x over previous
#include <cuda_runtime.h>
#include <math.h>

#define D 64
#define C 128
#define H 512
#define BATCH 4096
#define TM 16
#define NTHREADS 256

// Permuted + masked weights (built by prep kernel each launch; idempotent).
__device__ float g_W1p[(D + C) * H];   // [in][p]  in-major, masked, hidden perm
__device__ float g_W2p[H * H];         // [j][p]   j = reduction dim (sorted), p sorted
__device__ float g_W3pp[D * H * 2];    // [i][p][2] (mean col i, prescale col D+i), masked
__device__ float g_b1p[H];
__device__ float g_b2p[H];

// Hidden degrees: m_h[k] = (k % 63) + 1. Sorted by degree ascending (ties by k).
// Residues 0..7 occur 9x (degrees 1..8), residues 8..62 occur 8x (degrees 9..63).
__device__ __forceinline__ int permk(int p) {
    if (p < 72) { int d = p / 9; int t = p - 9 * d; return d + 63 * t; }
    int q = p - 72; int d8 = q >> 3; int t = q & 7; return 8 + d8 + 63 * t;
}
__device__ __forceinline__ int degp(int p) {
    return (p < 72) ? (p / 9 + 1) : ((p - 72) / 8 + 9);
}
// count of hidden units with degree <= d
__device__ __forceinline__ int cntd(int d) {
    return (d <= 0) ? 0 : (d <= 8 ? 9 * d : 8 * d + 8);
}

__global__ void prep_kernel(const float* __restrict__ W1, const float* __restrict__ b1,
                            const float* __restrict__ W2, const float* __restrict__ b2,
                            const float* __restrict__ W3) {
    const int NA = (D + C) * H;
    const int NB = H * H;
    const int NC = D * H;
    const int total = NA + NB + NC + 2 * H;
    for (int idx = blockIdx.x * blockDim.x + threadIdx.x; idx < total;
         idx += gridDim.x * blockDim.x) {
        if (idx < NA) {
            int in = idx >> 9, p = idx & 511;
            float m = (in < D) ? ((degp(p) >= in + 1) ? 1.f : 0.f) : 1.f;
            g_W1p[idx] = W1[in * H + permk(p)] * m;
        } else if (idx < NA + NB) {
            int t = idx - NA;
            int j = t >> 9, p = t & 511;
            g_W2p[t] = (degp(p) >= degp(j)) ? W2[permk(j) * H + permk(p)] : 0.f;
        } else if (idx < NA + NB + NC) {
            int t = idx - NA - NB;
            int i = t >> 9, p = t & 511;
            int k = permk(p);
            bool m = (degp(p) <= i);   // m_out = i+1 > deg  <=>  deg <= i
            g_W3pp[t * 2 + 0] = m ? W3[k * (2 * D) + i] : 0.f;
            g_W3pp[t * 2 + 1] = m ? W3[k * (2 * D) + D + i] : 0.f;
        } else {
            int t = idx - NA - NB - NC;
            if (t < H) g_b1p[t] = b1[permk(t)];
            else       g_b2p[t - H] = b2[permk(t - H)];
        }
    }
}

// Dynamic smem layout (floats):
//   h1s[H*TM]  : h1 (pre-act until finalized, then relu'd in place) [p][r]  32KB
//   ctx[C*TM]  : context, TRANSPOSED [c][r]                                  8KB
//   zsh[TM]    : z values of current step
//   red[2*TM]  : per-row mean (0..15) / prescale (16..31) partials
#define SMEM_FLOATS (H * TM + C * TM + TM + 2 * TM)
#define SMEM_BYTES (SMEM_FLOATS * 4)

__global__ __launch_bounds__(NTHREADS, 2)
void made_main(const float* __restrict__ qc, const float* __restrict__ eps,
               const float* __restrict__ b3, float* __restrict__ out) {
    extern __shared__ float sm[];
    float* h1s = sm;                 // [512][16]
    float* ctx = sm + H * TM;        // [128][16]
    float* zsh = ctx + C * TM;       // [16]
    float* red = zsh + TM;           // [32]

    const int tid  = threadIdx.x;
    const int r0   = blockIdx.x * TM;
    const int warp = tid >> 5, lane = tid & 31;
    const int rg    = lane & 3;               // row group: rows rg*4..rg*4+3
    const int cg    = lane >> 2;              // 0..7: col sub-offset cg*4
    const int rbase = rg << 2;
    const int wcol  = (warp << 5) + (cg << 2); // col offset within 256-chunk

    // ---- stage context transposed: ctx[c][r] ----
    for (int idx = tid; idx < TM * C; idx += NTHREADS) {
        int r = idx >> 7, c = idx & 127;
        ctx[c * TM + r] = qc[(r0 + r) * C + c];
    }
    if (tid < 2 * TM) red[tid] = 0.f;
    __syncthreads();

    // ---- h1_pre init: each thread owns 2 hidden units p, all 16 rows ----
    for (int p = tid; p < H; p += NTHREADS) {
        float acc[TM];
        float b = __ldg(&g_b1p[p]);
#pragma unroll
        for (int r = 0; r < TM; ++r) acc[r] = b;
        for (int c = 0; c < C; ++c) {
            float w = __ldg(&g_W1p[(D + c) * H + p]);
            float4 x0 = *(const float4*)&ctx[c * TM + 0];
            float4 x1 = *(const float4*)&ctx[c * TM + 4];
            float4 x2 = *(const float4*)&ctx[c * TM + 8];
            float4 x3 = *(const float4*)&ctx[c * TM + 12];
            acc[0]  += x0.x * w; acc[1]  += x0.y * w; acc[2]  += x0.z * w; acc[3]  += x0.w * w;
            acc[4]  += x1.x * w; acc[5]  += x1.y * w; acc[6]  += x1.z * w; acc[7]  += x1.w * w;
            acc[8]  += x2.x * w; acc[9]  += x2.y * w; acc[10] += x2.z * w; acc[11] += x2.w * w;
            acc[12] += x3.x * w; acc[13] += x3.y * w; acc[14] += x3.z * w; acc[15] += x3.w * w;
        }
#pragma unroll
        for (int r = 0; r < TM; ++r) h1s[p * TM + r] = acc[r];
    }

    // ---- 64 autoregressive steps ----
    for (int i = 0; i < D; ++i) {
        __syncthreads();   // prev h1 update + red reset visible
        const int n2 = cntd(i);               // needed h2 cols = sorted prefix
        float mm[4] = {0.f, 0.f, 0.f, 0.f};
        float pp[4] = {0.f, 0.f, 0.f, 0.f};
        bool any = false;

        for (int pc = 0; pc < n2; pc += 256) {
            const int wb = pc + (warp << 5);          // this warp's 32-col window
            if (wb >= n2) break;                       // warp-uniform skip
            any = true;
            const int lastneed = min(wb + 31, n2 - 1);
            const int jlimW = min(H, (cntd(degp(lastneed)) + 7) & ~7);
            const int mycol = pc + wcol;

            float4 b2v = __ldg((const float4*)&g_b2p[mycol]);
            float acc[4][4];
#pragma unroll
            for (int rr = 0; rr < 4; ++rr) {
                acc[rr][0] = b2v.x; acc[rr][1] = b2v.y;
                acc[rr][2] = b2v.z; acc[rr][3] = b2v.w;
            }

            const float* w2base = g_W2p + mycol;
            const float* hbase  = h1s + rbase;

            for (int jc = 0; jc < jlimW; jc += 8) {
                float4 w[8], h[8];
#pragma unroll
                for (int u = 0; u < 8; ++u)
                    w[u] = __ldg((const float4*)(w2base + (jc + u) * H));
#pragma unroll
                for (int u = 0; u < 8; ++u)
                    h[u] = *(const float4*)&hbase[(jc + u) * TM];
#pragma unroll
                for (int u = 0; u < 8; ++u) {
                    float4 hv = h[u], wv = w[u];
                    acc[0][0] += hv.x * wv.x; acc[0][1] += hv.x * wv.y;
                    acc[0][2] += hv.x * wv.z; acc[0][3] += hv.x * wv.w;
                    acc[1][0] += hv.y * wv.x; acc[1][1] += hv.y * wv.y;
                    acc[1][2] += hv.y * wv.z; acc[1][3] += hv.y * wv.w;
                    acc[2][0] += hv.z * wv.x; acc[2][1] += hv.z * wv.y;
                    acc[2][2] += hv.z * wv.z; acc[2][3] += hv.z * wv.w;
                    acc[3][0] += hv.w * wv.x; acc[3][1] += hv.w * wv.y;
                    acc[3][2] += hv.w * wv.z; acc[3][3] += hv.w * wv.w;
                }
            }

            // relu + project onto W3 cols (i, D+i); masked W3 zeroes out
            // cols with deg > i (their garbage h2 is harmless & finite).
            const float* w3 = g_W3pp + (((i << 9) + mycol) << 1);
            float4 wA = __ldg((const float4*)w3);        // (m0,p0,m1,p1)
            float4 wB = __ldg((const float4*)(w3 + 4));  // (m2,p2,m3,p3)
#pragma unroll
            for (int rr = 0; rr < 4; ++rr) {
                float h2;
                h2 = fmaxf(acc[rr][0], 0.f); mm[rr] += h2 * wA.x; pp[rr] += h2 * wA.y;
                h2 = fmaxf(acc[rr][1], 0.f); mm[rr] += h2 * wA.z; pp[rr] += h2 * wA.w;
                h2 = fmaxf(acc[rr][2], 0.f); mm[rr] += h2 * wB.x; pp[rr] += h2 * wB.y;
                h2 = fmaxf(acc[rr][3], 0.f); mm[rr] += h2 * wB.z; pp[rr] += h2 * wB.w;
            }
        }

        if (any) {
            // reduce over 8 col-groups within the warp (lane bits 2,3,4)
#pragma unroll
            for (int rr = 0; rr < 4; ++rr) {
                mm[rr] += __shfl_xor_sync(0xffffffffu, mm[rr], 4);
                mm[rr] += __shfl_xor_sync(0xffffffffu, mm[rr], 8);
                mm[rr] += __shfl_xor_sync(0xffffffffu, mm[rr], 16);
                pp[rr] += __shfl_xor_sync(0xffffffffu, pp[rr], 4);
                pp[rr] += __shfl_xor_sync(0xffffffffu, pp[rr], 8);
                pp[rr] += __shfl_xor_sync(0xffffffffu, pp[rr], 16);
            }
            if (lane < 4) {
#pragma unroll
                for (int rr = 0; rr < 4; ++rr) {
                    atomicAdd(&red[rbase + rr], mm[rr]);
                    atomicAdd(&red[TM + rbase + rr], pp[rr]);
                }
            }
        }
        __syncthreads();

        if (tid < TM) {
            float mean = red[tid] + b3[i];
            float pres = red[TM + tid] + b3[D + i];
            // stable softplus = max(x,0) + log1p(exp(-|x|))
            float sp = fmaxf(pres, 0.f) + log1pf(expf(-fabsf(pres)));
            float z = mean + sp * eps[(r0 + tid) * D + i];
            out[(r0 + tid) * D + i] = z;
            zsh[tid] = z;
            red[tid] = 0.f;                 // reset for next step
            red[TM + tid] = 0.f;
        }
        __syncthreads();

        // rank-1 h1 update: hidden units with deg >= i+1 (sorted suffix).
        // Rows with deg == i+1 are now finalized -> apply relu in place.
        const int s0  = n2;
        const int fin = cntd(i + 1);
        const int nupd = (H - s0) * TM;
        for (int u = tid; u < nupd; u += NTHREADS) {
            int p = s0 + (u >> 4), r = u & 15;
            float v = h1s[p * TM + r] + zsh[r] * __ldg(&g_W1p[i * H + p]);
            if (p < fin) v = fmaxf(v, 0.f);
            h1s[p * TM + r] = v;
        }
        // top-of-loop __syncthreads orders update before next step's reads
    }
}

extern "C" void kernel_launch(void* const* d_in, const int* in_sizes, int n_in,
                              void* d_out, int out_size) {
    const float* q   = (const float*)d_in[0];  // (4096, 128)
    const float* eps = (const float*)d_in[1];  // (4096, 64)
    const float* W1  = (const float*)d_in[2];  // (192, 512)
    const float* b1  = (const float*)d_in[3];  // (512,)
    const float* W2  = (const float*)d_in[4];  // (512, 512)
    const float* b2  = (const float*)d_in[5];  // (512,)
    const float* W3  = (const float*)d_in[6];  // (512, 128)
    const float* b3  = (const float*)d_in[7];  // (128,)
    float* out = (float*)d_out;                // (4096, 64)

    cudaFuncSetAttribute(made_main, cudaFuncAttributeMaxDynamicSharedMemorySize,
                         SMEM_BYTES);

    prep_kernel<<<408, 256>>>(W1, b1, W2, b2, W3);
    made_main<<<BATCH / TM, NTHREADS, SMEM_BYTES>>>(q, eps, b3, out);
}

// round 4
// speedup vs baseline: 2.1548x; 1.0682x over previous
#include <cuda_runtime.h>
#include <math.h>

#define D 64
#define C 128
#define H 512
#define BATCH 4096
#define TM 16
#define NTHREADS 256

// Permuted + masked weights (built by prep kernel each launch; idempotent).
__device__ float g_W1p[(D + C) * H];   // [in][p]  in-major, masked, hidden perm
__device__ float g_W2p[H * H];         // [j][p]   j = reduction dim (sorted), p sorted
__device__ float g_W3pp[D * H * 2];    // [i][p][2] (mean col i, prescale col D+i), masked
__device__ float g_b1p[H];
__device__ float g_b2p[H];

// Hidden degrees: m_h[k] = (k % 63) + 1. Sorted by degree ascending (ties by k).
// Residues 0..7 occur 9x (degrees 1..8), residues 8..62 occur 8x (degrees 9..63).
__device__ __forceinline__ int permk(int p) {
    if (p < 72) { int d = p / 9; int t = p - 9 * d; return d + 63 * t; }
    int q = p - 72; int d8 = q >> 3; int t = q & 7; return 8 + d8 + 63 * t;
}
__device__ __forceinline__ int degp(int p) {
    return (p < 72) ? (p / 9 + 1) : ((p - 72) / 8 + 9);
}
// count of hidden units with degree <= d
__device__ __forceinline__ int cntd(int d) {
    return (d <= 0) ? 0 : (d <= 8 ? 9 * d : 8 * d + 8);
}

__global__ void prep_kernel(const float* __restrict__ W1, const float* __restrict__ b1,
                            const float* __restrict__ W2, const float* __restrict__ b2,
                            const float* __restrict__ W3) {
    const int NA = (D + C) * H;
    const int NB = H * H;
    const int NC = D * H;
    const int total = NA + NB + NC + 2 * H;
    for (int idx = blockIdx.x * blockDim.x + threadIdx.x; idx < total;
         idx += gridDim.x * blockDim.x) {
        if (idx < NA) {
            int in = idx >> 9, p = idx & 511;
            float m = (in < D) ? ((degp(p) >= in + 1) ? 1.f : 0.f) : 1.f;
            g_W1p[idx] = W1[in * H + permk(p)] * m;
        } else if (idx < NA + NB) {
            int t = idx - NA;
            int j = t >> 9, p = t & 511;
            g_W2p[t] = (degp(p) >= degp(j)) ? W2[permk(j) * H + permk(p)] : 0.f;
        } else if (idx < NA + NB + NC) {
            int t = idx - NA - NB;
            int i = t >> 9, p = t & 511;
            int k = permk(p);
            bool m = (degp(p) <= i);   // m_out = i+1 > deg  <=>  deg <= i
            g_W3pp[t * 2 + 0] = m ? W3[k * (2 * D) + i] : 0.f;
            g_W3pp[t * 2 + 1] = m ? W3[k * (2 * D) + D + i] : 0.f;
        } else {
            int t = idx - NA - NB - NC;
            if (t < H) g_b1p[t] = b1[permk(t)];
            else       g_b2p[t - H] = b2[permk(t - H)];
        }
    }
}

// Dynamic smem layout (floats):
//   h1s[H*TM]  : h1 (pre-act until finalized, then relu'd in place) [p][r]  32KB
//   ctx[C*TM]  : context, TRANSPOSED [c][r]                                  8KB
//   zsh[TM]    : z values of current step
//   red[2*TM]  : per-row mean (0..15) / prescale (16..31) partials
#define SMEM_FLOATS (H * TM + C * TM + TM + 2 * TM)
#define SMEM_BYTES (SMEM_FLOATS * 4)

__global__ __launch_bounds__(NTHREADS, 2)
void made_main(const float* __restrict__ qc, const float* __restrict__ eps,
               const float* __restrict__ b3, float* __restrict__ out) {
    extern __shared__ float sm[];
    float* h1s = sm;                 // [512][16]
    float* ctx = sm + H * TM;        // [128][16]
    float* zsh = ctx + C * TM;       // [16]
    float* red = zsh + TM;           // [32]

    const int tid  = threadIdx.x;
    const int r0   = blockIdx.x * TM;
    const int warp = tid >> 5, lane = tid & 31;
    const int rg    = lane & 3;               // row group: rows rg*4..rg*4+3
    const int cg    = lane >> 2;              // 0..7: col sub-offset cg*4
    const int rbase = rg << 2;

    // ---- stage context transposed: ctx[c][r] ----
    for (int idx = tid; idx < TM * C; idx += NTHREADS) {
        int r = idx >> 7, c = idx & 127;
        ctx[c * TM + r] = qc[(r0 + r) * C + c];
    }
    if (tid < 2 * TM) red[tid] = 0.f;
    __syncthreads();

    // ---- h1_pre init: each thread owns 2 hidden units p, all 16 rows ----
    for (int p = tid; p < H; p += NTHREADS) {
        float acc[TM];
        float b = __ldg(&g_b1p[p]);
#pragma unroll
        for (int r = 0; r < TM; ++r) acc[r] = b;
        for (int c = 0; c < C; ++c) {
            float w = __ldg(&g_W1p[(D + c) * H + p]);
            float4 x0 = *(const float4*)&ctx[c * TM + 0];
            float4 x1 = *(const float4*)&ctx[c * TM + 4];
            float4 x2 = *(const float4*)&ctx[c * TM + 8];
            float4 x3 = *(const float4*)&ctx[c * TM + 12];
            acc[0]  += x0.x * w; acc[1]  += x0.y * w; acc[2]  += x0.z * w; acc[3]  += x0.w * w;
            acc[4]  += x1.x * w; acc[5]  += x1.y * w; acc[6]  += x1.z * w; acc[7]  += x1.w * w;
            acc[8]  += x2.x * w; acc[9]  += x2.y * w; acc[10] += x2.z * w; acc[11] += x2.w * w;
            acc[12] += x3.x * w; acc[13] += x3.y * w; acc[14] += x3.z * w; acc[15] += x3.w * w;
        }
#pragma unroll
        for (int r = 0; r < TM; ++r) h1s[p * TM + r] = acc[r];
    }

    // ---- 64 autoregressive steps ----
    for (int i = 0; i < D; ++i) {
        __syncthreads();   // prev h1 update + red reset visible
        const int n2   = cntd(i);             // needed h2 cols = sorted prefix
        const int nwin = (n2 + 31) >> 5;      // 32-col windows in use (<=16)
        float mm[4] = {0.f, 0.f, 0.f, 0.f};
        float pp[4] = {0.f, 0.f, 0.f, 0.f};
        bool any = false;

        // Serpentine load-balanced window assignment: warp w handles windows
        // {nwin-1-w, nwin-16+w} (those >= 0). Pair cost is ~constant across
        // warps since jlim(window) grows ~linearly with the window index.
#pragma unroll
        for (int s = 0; s < 2; ++s) {
            const int w = (s == 0) ? (nwin - 1 - warp) : (nwin - 16 + warp);
            if (w < 0) continue;               // warp-uniform predicate
            any = true;
            const int wb = w << 5;
            const int lastneed = min(wb + 31, n2 - 1);
            const int jlimW = min(H, (cntd(degp(lastneed)) + 7) & ~7);
            const int mycol = wb + (cg << 2);

            float4 b2v = __ldg((const float4*)&g_b2p[mycol]);
            float acc[4][4];
#pragma unroll
            for (int rr = 0; rr < 4; ++rr) {
                acc[rr][0] = b2v.x; acc[rr][1] = b2v.y;
                acc[rr][2] = b2v.z; acc[rr][3] = b2v.w;
            }

            const float* w2base = g_W2p + mycol;
            const float* hbase  = h1s + rbase;

            for (int jc = 0; jc < jlimW; jc += 8) {
                float4 wv4[8], h[8];
#pragma unroll
                for (int u = 0; u < 8; ++u)
                    wv4[u] = __ldg((const float4*)(w2base + (jc + u) * H));
#pragma unroll
                for (int u = 0; u < 8; ++u)
                    h[u] = *(const float4*)&hbase[(jc + u) * TM];
#pragma unroll
                for (int u = 0; u < 8; ++u) {
                    float4 hv = h[u], wv = wv4[u];
                    acc[0][0] += hv.x * wv.x; acc[0][1] += hv.x * wv.y;
                    acc[0][2] += hv.x * wv.z; acc[0][3] += hv.x * wv.w;
                    acc[1][0] += hv.y * wv.x; acc[1][1] += hv.y * wv.y;
                    acc[1][2] += hv.y * wv.z; acc[1][3] += hv.y * wv.w;
                    acc[2][0] += hv.z * wv.x; acc[2][1] += hv.z * wv.y;
                    acc[2][2] += hv.z * wv.z; acc[2][3] += hv.z * wv.w;
                    acc[3][0] += hv.w * wv.x; acc[3][1] += hv.w * wv.y;
                    acc[3][2] += hv.w * wv.z; acc[3][3] += hv.w * wv.w;
                }
            }

            // relu + project onto W3 cols (i, D+i); masked W3 zeroes out
            // cols with deg > i (their garbage h2 is harmless & finite).
            const float* w3 = g_W3pp + (((i << 9) + mycol) << 1);
            float4 wA = __ldg((const float4*)w3);        // (m0,p0,m1,p1)
            float4 wB = __ldg((const float4*)(w3 + 4));  // (m2,p2,m3,p3)
#pragma unroll
            for (int rr = 0; rr < 4; ++rr) {
                float h2;
                h2 = fmaxf(acc[rr][0], 0.f); mm[rr] += h2 * wA.x; pp[rr] += h2 * wA.y;
                h2 = fmaxf(acc[rr][1], 0.f); mm[rr] += h2 * wA.z; pp[rr] += h2 * wA.w;
                h2 = fmaxf(acc[rr][2], 0.f); mm[rr] += h2 * wB.x; pp[rr] += h2 * wB.y;
                h2 = fmaxf(acc[rr][3], 0.f); mm[rr] += h2 * wB.z; pp[rr] += h2 * wB.w;
            }
        }

        if (any) {
            // reduce over 8 col-groups within the warp (lane bits 2,3,4)
#pragma unroll
            for (int rr = 0; rr < 4; ++rr) {
                mm[rr] += __shfl_xor_sync(0xffffffffu, mm[rr], 4);
                mm[rr] += __shfl_xor_sync(0xffffffffu, mm[rr], 8);
                mm[rr] += __shfl_xor_sync(0xffffffffu, mm[rr], 16);
                pp[rr] += __shfl_xor_sync(0xffffffffu, pp[rr], 4);
                pp[rr] += __shfl_xor_sync(0xffffffffu, pp[rr], 8);
                pp[rr] += __shfl_xor_sync(0xffffffffu, pp[rr], 16);
            }
            if (lane < 4) {
#pragma unroll
                for (int rr = 0; rr < 4; ++rr) {
                    atomicAdd(&red[rbase + rr], mm[rr]);
                    atomicAdd(&red[TM + rbase + rr], pp[rr]);
                }
            }
        }
        __syncthreads();

        if (tid < TM) {
            float mean = red[tid] + b3[i];
            float pres = red[TM + tid] + b3[D + i];
            // stable softplus = max(x,0) + log1p(exp(-|x|))
            float sp = fmaxf(pres, 0.f) + log1pf(expf(-fabsf(pres)));
            float z = mean + sp * eps[(r0 + tid) * D + i];
            out[(r0 + tid) * D + i] = z;
            zsh[tid] = z;
            red[tid] = 0.f;                 // reset for next step
            red[TM + tid] = 0.f;
        }
        __syncthreads();

        // rank-1 h1 update: hidden units with deg >= i+1 (sorted suffix).
        // Rows with deg == i+1 are now finalized -> apply relu in place.
        const int s0  = n2;
        const int fin = cntd(i + 1);
        const int nupd = (H - s0) * TM;
        for (int u = tid; u < nupd; u += NTHREADS) {
            int p = s0 + (u >> 4), r = u & 15;
            float v = h1s[p * TM + r] + zsh[r] * __ldg(&g_W1p[i * H + p]);
            if (p < fin) v = fmaxf(v, 0.f);
            h1s[p * TM + r] = v;
        }
        // top-of-loop __syncthreads orders update before next step's reads
    }
}

extern "C" void kernel_launch(void* const* d_in, const int* in_sizes, int n_in,
                              void* d_out, int out_size) {
    const float* q   = (const float*)d_in[0];  // (4096, 128)
    const float* eps = (const float*)d_in[1];  // (4096, 64)
    const float* W1  = (const float*)d_in[2];  // (192, 512)
    const float* b1  = (const float*)d_in[3];  // (512,)
    const float* W2  = (const float*)d_in[4];  // (512, 512)
    const float* b2  = (const float*)d_in[5];  // (512,)
    const float* W3  = (const float*)d_in[6];  // (512, 128)
    const float* b3  = (const float*)d_in[7];  // (128,)
    float* out = (float*)d_out;                // (4096, 64)

    cudaFuncSetAttribute(made_main, cudaFuncAttributeMaxDynamicSharedMemorySize,
                         SMEM_BYTES);

    prep_kernel<<<408, 256>>>(W1, b1, W2, b2, W3);
    made_main<<<BATCH / TM, NTHREADS, SMEM_BYTES>>>(q, eps, b3, out);
}